// round 6
// baseline (speedup 1.0000x reference)
#include <cuda_runtime.h>
#include <cstdint>

#define DIM 128
#define MAXN 50176
#define MAXE 600000
#define BM 128
#define BK 32
#define AP 36               // padded smem row pitch in words (bank-conflict-free)

__device__ float g_hpre[MAXN * DIM];   // x + agg
__device__ float g_h1[MAXN * DIM];     // Linear1 output, pre-BN
__device__ float g_stats[2 * DIM];     // colsum | colsumsq
__device__ int   g_cnt[MAXN];          // per-dst edge counts
__device__ int   g_off[MAXN + 1];      // CSR offsets
__device__ int   g_cur[MAXN];          // fill cursors
__device__ int   g_srcs[MAXE];         // CSR src lists

// ---------------------------------------------------------------------------
// K0: zero counters + stats
// ---------------------------------------------------------------------------
__global__ void zero_kernel(int n) {
    int gid = blockIdx.x * blockDim.x + threadIdx.x;
    if (gid < 2 * DIM) g_stats[gid] = 0.0f;
    if (gid < n) g_cnt[gid] = 0;
}

// ---------------------------------------------------------------------------
// K1: histogram of dst
// ---------------------------------------------------------------------------
__global__ void hist_kernel(const int* __restrict__ ei, int n_edges) {
    int e = blockIdx.x * blockDim.x + threadIdx.x;
    if (e < n_edges) atomicAdd(&g_cnt[ei[n_edges + e]], 1);
}

// ---------------------------------------------------------------------------
// K2: single-block exclusive prefix scan of g_cnt -> g_off, g_cur
// ---------------------------------------------------------------------------
__global__ __launch_bounds__(1024, 1)
void scan_kernel(int n) {
    __shared__ int warp_tot[32];
    int tid = threadIdx.x;
    int lane = tid & 31, wid = tid >> 5;
    int CH = (n + 1023) >> 10;
    int beg = tid * CH;
    int end = min(beg + CH, n);

    int s = 0;
    for (int i = beg; i < end; i++) s += g_cnt[i];

    int v = s;
#pragma unroll
    for (int o = 1; o < 32; o <<= 1) {
        int t = __shfl_up_sync(0xffffffff, v, o);
        if (lane >= o) v += t;
    }
    if (lane == 31) warp_tot[wid] = v;
    __syncthreads();
    if (wid == 0) {
        int w = warp_tot[lane];
#pragma unroll
        for (int o = 1; o < 32; o <<= 1) {
            int t = __shfl_up_sync(0xffffffff, w, o);
            if (lane >= o) w += t;
        }
        warp_tot[lane] = w;
    }
    __syncthreads();

    int run = v - s + (wid > 0 ? warp_tot[wid - 1] : 0);   // exclusive prefix
    for (int i = beg; i < end; i++) {
        int c = g_cnt[i];
        g_off[i] = run;
        g_cur[i] = run;
        run += c;
    }
    if (tid == 1023) g_off[n] = run;
}

// ---------------------------------------------------------------------------
// K3: fill CSR src lists
// ---------------------------------------------------------------------------
__global__ void fill_kernel(const int* __restrict__ ei, int n_edges) {
    int e = blockIdx.x * blockDim.x + threadIdx.x;
    if (e < n_edges) {
        int dst = ei[n_edges + e];
        int pos = atomicAdd(&g_cur[dst], 1);
        g_srcs[pos] = ei[e];
    }
}

// ---------------------------------------------------------------------------
// K4: gather  h_pre[v] = x[v] + sum_{u in N(v)} x[u]   (warp per node)
// ---------------------------------------------------------------------------
__global__ void gather_kernel(const float* __restrict__ x, int n_nodes) {
    int g = blockIdx.x * blockDim.x + threadIdx.x;
    int node = g >> 5;
    int lane = g & 31;
    if (node >= n_nodes) return;
    float4 acc = __ldg((const float4*)(x + (size_t)node * DIM) + lane);
    int beg = g_off[node];
    int end = g_off[node + 1];
    for (int i = beg; i < end; i++) {
        int s = g_srcs[i];
        float4 v = __ldg((const float4*)(x + (size_t)s * DIM) + lane);
        acc.x += v.x; acc.y += v.y; acc.z += v.z; acc.w += v.w;
    }
    *((float4*)(g_hpre + (size_t)node * DIM) + lane) = acc;
}

// ---------------------------------------------------------------------------
__device__ __forceinline__ unsigned f2tf(float f) {
    unsigned r;
    asm("cvt.rna.tf32.f32 %0, %1;" : "=r"(r) : "f"(f));
    return r;
}

__device__ __forceinline__ void mma_tf32(float* c, const unsigned* a, const unsigned* b) {
    asm volatile(
        "mma.sync.aligned.m16n8k8.row.col.f32.tf32.tf32.f32 "
        "{%0,%1,%2,%3}, {%4,%5,%6,%7}, {%8,%9}, {%0,%1,%2,%3};"
        : "+f"(c[0]), "+f"(c[1]), "+f"(c[2]), "+f"(c[3])
        : "r"(a[0]), "r"(a[1]), "r"(a[2]), "r"(a[3]), "r"(b[0]), "r"(b[1]));
}

// ---------------------------------------------------------------------------
// tf32 tensor-core GEMM, 128x128 block tile, 8 warps (4m x 2n), 32x64 warp tile
// PHASE 1: h1 = h_pre @ W1^T + b1 ; BN column sum/sumsq
// PHASE 2: out = lrelu_.2( lrelu_.01(bn(h1)) @ W2^T + x @ Wres^T + b2 ), K=256
//          (BN scale/shift computed per-block from g_stats -- bn fused)
// ---------------------------------------------------------------------------
template <int PHASE>
__global__ __launch_bounds__(256, 2)
void gemm_kernel(const float* __restrict__ Ax,
                 const float* __restrict__ W0,
                 const float* __restrict__ W1p,
                 const float* __restrict__ bias,
                 const float* __restrict__ gamma,
                 const float* __restrict__ beta,
                 float* __restrict__ outp,
                 int M, float invM) {
    __shared__ unsigned As[BM * AP];
    __shared__ unsigned Ws[DIM * AP];
    __shared__ float s_sum[DIM];
    __shared__ float s_sq[DIM];
    __shared__ float ssc[DIM];
    __shared__ float ssh[DIM];

    const int tid  = threadIdx.x;
    const int wid  = tid >> 5;
    const int lane = tid & 31;
    const int g    = lane >> 2;
    const int tg   = lane & 3;
    const int wm   = wid & 3;
    const int wn   = wid >> 2;
    const int rowBase = blockIdx.x * BM;

    if (PHASE == 1) {
        if (tid < DIM) { s_sum[tid] = 0.f; s_sq[tid] = 0.f; }
    } else {
        if (tid < DIM) {
            float mu  = g_stats[tid] * invM;
            float var = g_stats[DIM + tid] * invM - mu * mu;
            float rstd = rsqrtf(var + 1e-5f);
            float s = gamma[tid] * rstd;
            ssc[tid] = s;
            ssh[tid] = beta[tid] - mu * s;
        }
    }
    __syncthreads();

    float acc[2][8][4];
#pragma unroll
    for (int i = 0; i < 2; i++)
#pragma unroll
        for (int j = 0; j < 8; j++)
#pragma unroll
            for (int r = 0; r < 4; r++) acc[i][j][r] = 0.f;

    const int NCHUNK = (PHASE == 1) ? 4 : 8;

#pragma unroll 1
    for (int kc = 0; kc < NCHUNK; kc++) {
        const int kbase = kc * BK;

        // ---- A tile ----
#pragma unroll
        for (int t = 0; t < 4; t++) {
            int idx = tid + t * 256;
            int m = idx >> 3;
            int f4 = (idx & 7) * 4;
            int gr = rowBase + m;
            float4 v = make_float4(0.f, 0.f, 0.f, 0.f);
            if (PHASE == 1) {
                if (gr < M) v = *(const float4*)(g_hpre + (size_t)gr * DIM + kbase + f4);
            } else {
                if (kbase < DIM) {
                    if (gr < M) {
                        v = *(const float4*)(g_h1 + (size_t)gr * DIM + kbase + f4);
                        int kk = kbase + f4;
                        v.x = v.x * ssc[kk + 0] + ssh[kk + 0];
                        v.y = v.y * ssc[kk + 1] + ssh[kk + 1];
                        v.z = v.z * ssc[kk + 2] + ssh[kk + 2];
                        v.w = v.w * ssc[kk + 3] + ssh[kk + 3];
                        v.x = v.x > 0.f ? v.x : 0.01f * v.x;
                        v.y = v.y > 0.f ? v.y : 0.01f * v.y;
                        v.z = v.z > 0.f ? v.z : 0.01f * v.z;
                        v.w = v.w > 0.f ? v.w : 0.01f * v.w;
                    }
                } else {
                    if (gr < M) v = *(const float4*)(Ax + (size_t)gr * DIM + (kbase - DIM) + f4);
                }
            }
            unsigned* dstp = As + m * AP + f4;
            dstp[0] = f2tf(v.x); dstp[1] = f2tf(v.y);
            dstp[2] = f2tf(v.z); dstp[3] = f2tf(v.w);
        }

        // ---- W tile ----
#pragma unroll
        for (int t = 0; t < 4; t++) {
            int idx = tid + t * 256;
            int n = idx >> 3;
            int f4 = (idx & 7) * 4;
            const float* Wsrc;
            int kk;
            if (PHASE == 1) { Wsrc = W0; kk = kbase; }
            else if (kbase < DIM) { Wsrc = W0; kk = kbase; }
            else { Wsrc = W1p; kk = kbase - DIM; }
            float4 v = *(const float4*)(Wsrc + (size_t)n * DIM + kk + f4);
            unsigned* dstp = Ws + n * AP + f4;
            dstp[0] = f2tf(v.x); dstp[1] = f2tf(v.y);
            dstp[2] = f2tf(v.z); dstp[3] = f2tf(v.w);
        }
        __syncthreads();

        // ---- 4 k8-steps of m16n8k8 MMAs ----
#pragma unroll
        for (int k8 = 0; k8 < 4; k8++) {
            const int kof = k8 * 8;
            unsigned afrag[2][4];
#pragma unroll
            for (int mt = 0; mt < 2; mt++) {
                int r0 = wm * 32 + mt * 16 + g;
                afrag[mt][0] = As[(r0    ) * AP + kof + tg];
                afrag[mt][1] = As[(r0 + 8) * AP + kof + tg];
                afrag[mt][2] = As[(r0    ) * AP + kof + tg + 4];
                afrag[mt][3] = As[(r0 + 8) * AP + kof + tg + 4];
            }
            unsigned bfrag[8][2];
#pragma unroll
            for (int nt = 0; nt < 8; nt++) {
                int n0 = wn * 64 + nt * 8 + g;
                bfrag[nt][0] = Ws[n0 * AP + kof + tg];
                bfrag[nt][1] = Ws[n0 * AP + kof + tg + 4];
            }
#pragma unroll
            for (int mt = 0; mt < 2; mt++)
#pragma unroll
                for (int nt = 0; nt < 8; nt++)
                    mma_tf32(acc[mt][nt], afrag[mt], bfrag[nt]);
        }
        __syncthreads();
    }

    // ---- epilogue ----
    if (PHASE == 1) {
        float tsum[8][2], tsq[8][2];
#pragma unroll
        for (int nt = 0; nt < 8; nt++)
            tsum[nt][0] = tsum[nt][1] = tsq[nt][0] = tsq[nt][1] = 0.f;

#pragma unroll
        for (int mt = 0; mt < 2; mt++) {
#pragma unroll
            for (int half = 0; half < 2; half++) {
                int gr = rowBase + wm * 32 + mt * 16 + g + half * 8;
                if (gr < M) {
#pragma unroll
                    for (int nt = 0; nt < 8; nt++) {
                        int c = wn * 64 + nt * 8 + tg * 2;
                        float v0 = acc[mt][nt][half * 2 + 0] + __ldg(bias + c);
                        float v1 = acc[mt][nt][half * 2 + 1] + __ldg(bias + c + 1);
                        tsum[nt][0] += v0;  tsum[nt][1] += v1;
                        tsq[nt][0] += v0 * v0;  tsq[nt][1] += v1 * v1;
                        *(float2*)(g_h1 + (size_t)gr * DIM + c) = make_float2(v0, v1);
                    }
                }
            }
        }
#pragma unroll
        for (int nt = 0; nt < 8; nt++) {
#pragma unroll
            for (int h = 0; h < 2; h++) {
#pragma unroll
                for (int ofs = 4; ofs < 32; ofs <<= 1) {
                    tsum[nt][h] += __shfl_xor_sync(0xffffffff, tsum[nt][h], ofs);
                    tsq[nt][h]  += __shfl_xor_sync(0xffffffff, tsq[nt][h], ofs);
                }
            }
        }
        if (g == 0) {
#pragma unroll
            for (int nt = 0; nt < 8; nt++) {
                int c = wn * 64 + nt * 8 + tg * 2;
                atomicAdd(&s_sum[c],     tsum[nt][0]);
                atomicAdd(&s_sum[c + 1], tsum[nt][1]);
                atomicAdd(&s_sq[c],      tsq[nt][0]);
                atomicAdd(&s_sq[c + 1],  tsq[nt][1]);
            }
        }
        __syncthreads();
        if (tid < DIM) {
            atomicAdd(&g_stats[tid],       s_sum[tid]);
            atomicAdd(&g_stats[DIM + tid], s_sq[tid]);
        }
    } else {
#pragma unroll
        for (int mt = 0; mt < 2; mt++) {
#pragma unroll
            for (int half = 0; half < 2; half++) {
                int gr = rowBase + wm * 32 + mt * 16 + g + half * 8;
                if (gr < M) {
#pragma unroll
                    for (int nt = 0; nt < 8; nt++) {
                        int c = wn * 64 + nt * 8 + tg * 2;
                        float v0 = acc[mt][nt][half * 2 + 0] + __ldg(bias + c);
                        float v1 = acc[mt][nt][half * 2 + 1] + __ldg(bias + c + 1);
                        v0 = v0 > 0.f ? v0 : 0.2f * v0;
                        v1 = v1 > 0.f ? v1 : 0.2f * v1;
                        *(float2*)(outp + (size_t)gr * DIM + c) = make_float2(v0, v1);
                    }
                }
            }
        }
    }
}

// ---------------------------------------------------------------------------
extern "C" void kernel_launch(void* const* d_in, const int* in_sizes, int n_in,
                              void* d_out, int out_size) {
    const float* x     = (const float*)d_in[0];
    const int* ei      = (const int*)d_in[1];
    const float* W1    = (const float*)d_in[2];
    const float* b1    = (const float*)d_in[3];
    const float* gamma = (const float*)d_in[4];
    const float* beta  = (const float*)d_in[5];
    const float* W2    = (const float*)d_in[6];
    const float* b2    = (const float*)d_in[7];
    const float* Wres  = (const float*)d_in[8];
    float* out         = (float*)d_out;

    int M = in_sizes[0] / DIM;       // 50000
    int E = in_sizes[1] / 2;         // 600000

    zero_kernel<<<(M + 255) / 256, 256>>>(M);
    hist_kernel<<<(E + 255) / 256, 256>>>(ei, E);
    scan_kernel<<<1, 1024>>>(M);
    fill_kernel<<<(E + 255) / 256, 256>>>(ei, E);
    {
        long long work = (long long)M * 32;
        int blocks = (int)((work + 255) / 256);
        gather_kernel<<<blocks, 256>>>(x, M);
    }
    int gb = (M + BM - 1) / BM;
    float invM = 1.0f / (float)M;
    gemm_kernel<1><<<gb, 256>>>(nullptr, W1, nullptr, b1, nullptr, nullptr, nullptr, M, invM);
    gemm_kernel<2><<<gb, 256>>>(x, W2, Wres, b2, gamma, beta, out, M, invM);
}

// round 7
// speedup vs baseline: 1.3590x; 1.3590x over previous
#include <cuda_runtime.h>
#include <cstdint>

#define DIM 128
#define MAXN 50176
#define BM 128
#define BK 32
#define AP 36                   // padded smem row pitch (words), conflict-free
#define TILEW (BM * AP)         // 4608 words per tile buffer
#define SMEM_BYTES (4 * TILEW * 4)   // 2 A bufs + 2 W bufs = 73728 B

__device__ float g_hpre[MAXN * DIM];       // x + agg
__device__ float g_h1[MAXN * DIM];         // Linear1 out; bnfix transforms in place
__device__ float g_stats[2 * DIM];         // colsum | colsumsq
__device__ unsigned g_w1[DIM * DIM];       // tf32-rounded weights
__device__ unsigned g_w2[DIM * DIM];
__device__ unsigned g_wres[DIM * DIM];

// ---------------------------------------------------------------------------
__device__ __forceinline__ unsigned f2tf(float f) {
    unsigned r;
    asm("cvt.rna.tf32.f32 %0, %1;" : "=r"(r) : "f"(f));
    return r;
}

__device__ __forceinline__ void mma_tf32(float* c, const unsigned* a, const unsigned* b) {
    asm volatile(
        "mma.sync.aligned.m16n8k8.row.col.f32.tf32.tf32.f32 "
        "{%0,%1,%2,%3}, {%4,%5,%6,%7}, {%8,%9}, {%0,%1,%2,%3};"
        : "+f"(c[0]), "+f"(c[1]), "+f"(c[2]), "+f"(c[3])
        : "r"(a[0]), "r"(a[1]), "r"(a[2]), "r"(a[3]), "r"(b[0]), "r"(b[1]));
}

__device__ __forceinline__ void cp16(unsigned smem_dst, const void* gsrc) {
    asm volatile("cp.async.ca.shared.global [%0], [%1], 16;"
                 :: "r"(smem_dst), "l"(gsrc));
}

// ---------------------------------------------------------------------------
// prep: tf32-round all weight matrices; zero BN stats
// ---------------------------------------------------------------------------
__global__ void prep_kernel(const float* __restrict__ W1,
                            const float* __restrict__ W2,
                            const float* __restrict__ Wres) {
    int i = blockIdx.x * blockDim.x + threadIdx.x;
    if (i < 2 * DIM) g_stats[i] = 0.0f;
    if (i < DIM * DIM) {
        g_w1[i]   = f2tf(W1[i]);
        g_w2[i]   = f2tf(W2[i]);
        g_wres[i] = f2tf(Wres[i]);
    }
}

// ---------------------------------------------------------------------------
__global__ void init_kernel(const float* __restrict__ x, int n4) {
    int gid = blockIdx.x * blockDim.x + threadIdx.x;
    if (gid < n4) ((float4*)g_hpre)[gid] = ((const float4*)x)[gid];
}

// ---------------------------------------------------------------------------
// scatter-add: warp per edge, lane = 4 floats -> LDG.128 + red.global.v4.f32
// ---------------------------------------------------------------------------
__global__ void scatter_kernel(const float* __restrict__ x,
                               const int* __restrict__ ei,
                               int n_edges) {
    int g = blockIdx.x * blockDim.x + threadIdx.x;
    int e = g >> 5;
    int lane = g & 31;
    if (e >= n_edges) return;
    int src = ei[e];
    int dst = ei[n_edges + e];
    const float4* xs = (const float4*)(x + (size_t)src * DIM) + lane;
    float4* hd = (float4*)(g_hpre + (size_t)dst * DIM) + lane;
    float4 v = __ldg(xs);
    asm volatile("red.global.add.v4.f32 [%0], {%1, %2, %3, %4};"
                 :: "l"(hd), "f"(v.x), "f"(v.y), "f"(v.z), "f"(v.w)
                 : "memory");
}

// ---------------------------------------------------------------------------
// bnfix: g_h1 <- tf32_rna( lrelu_0.01( h1 * scale + shift ) )  in place
// ---------------------------------------------------------------------------
__global__ void bnfix_kernel(const float* __restrict__ gamma,
                             const float* __restrict__ beta,
                             float invM, int total4) {
    __shared__ float ssc[DIM];
    __shared__ float ssh[DIM];
    int tid = threadIdx.x;
    if (tid < DIM) {
        float mu  = g_stats[tid] * invM;
        float var = g_stats[DIM + tid] * invM - mu * mu;
        float rstd = rsqrtf(var + 1e-5f);
        float s = gamma[tid] * rstd;
        ssc[tid] = s;
        ssh[tid] = beta[tid] - mu * s;
    }
    __syncthreads();
    int i = blockIdx.x * blockDim.x + tid;
    if (i < total4) {
        float4 v = ((float4*)g_h1)[i];
        int c = (i & 31) * 4;        // DIM/4 = 32 float4 per row
        v.x = fmaf(v.x, ssc[c + 0], ssh[c + 0]);
        v.y = fmaf(v.y, ssc[c + 1], ssh[c + 1]);
        v.z = fmaf(v.z, ssc[c + 2], ssh[c + 2]);
        v.w = fmaf(v.w, ssc[c + 3], ssh[c + 3]);
        v.x = v.x > 0.f ? v.x : 0.01f * v.x;
        v.y = v.y > 0.f ? v.y : 0.01f * v.y;
        v.z = v.z > 0.f ? v.z : 0.01f * v.z;
        v.w = v.w > 0.f ? v.w : 0.01f * v.w;
        v.x = __uint_as_float(f2tf(v.x));
        v.y = __uint_as_float(f2tf(v.y));
        v.z = __uint_as_float(f2tf(v.z));
        v.w = __uint_as_float(f2tf(v.w));
        ((float4*)g_h1)[i] = v;
    }
}

// ---------------------------------------------------------------------------
// Pipelined tf32 GEMM: cp.async double-buffered A and W chunk streams.
// PHASE 1: h1 = h_pre @ W1^T + b1 ; BN column sum/sumsq     (K=128)
// PHASE 2: out = lrelu_.2( h1' @ W2^T + x @ Wres^T + b2 )   (K=256)
// ---------------------------------------------------------------------------
template <int PHASE>
__global__ __launch_bounds__(256, 2)
void gemm_kernel(const float* __restrict__ Ax,      // phase2: x
                 const float* __restrict__ bias,
                 float* __restrict__ outp,
                 int M) {
    extern __shared__ unsigned smem[];
    unsigned* Abuf = smem;                 // [2][TILEW]
    unsigned* Wbuf = smem + 2 * TILEW;     // [2][TILEW]
    __shared__ float s_sum[DIM];
    __shared__ float s_sq[DIM];

    const int tid  = threadIdx.x;
    const int wid  = tid >> 5;
    const int lane = tid & 31;
    const int g    = lane >> 2;
    const int tg   = lane & 3;
    const int wm   = wid & 3;
    const int wn   = wid >> 2;
    const int rowBase = blockIdx.x * BM;

    if (PHASE == 1 && tid < DIM) { s_sum[tid] = 0.f; s_sq[tid] = 0.f; }

    const int NCHUNK = (PHASE == 1) ? 4 : 8;

    // ---- chunk loader: 4 x 16B cp.async for A, 4 for W, one commit ----
    auto load_chunk = [&](int kc, int bufidx) {
        const int kbase = kc * BK;
        unsigned* Ad = Abuf + bufidx * TILEW;
        unsigned* Wd = Wbuf + bufidx * TILEW;
#pragma unroll
        for (int t = 0; t < 4; t++) {
            int idx = tid + t * 256;
            int m = idx >> 3;
            int f4 = (idx & 7) * 4;
            // A source
            const void* asrc;
            if (PHASE == 1) {
                asrc = g_hpre + (size_t)(rowBase + m) * DIM + kbase + f4;
            } else if (kbase < DIM) {
                asrc = g_h1 + (size_t)(rowBase + m) * DIM + kbase + f4;
            } else {
                int gr = rowBase + m;
                if (gr >= M) gr = M - 1;           // x has exactly M rows
                asrc = Ax + (size_t)gr * DIM + (kbase - DIM) + f4;
            }
            cp16((unsigned)__cvta_generic_to_shared(Ad + m * AP + f4), asrc);
            // W source (n == m decomposition)
            const unsigned* wsrc;
            if (PHASE == 1)            wsrc = g_w1   + m * DIM + kbase + f4;
            else if (kbase < DIM)      wsrc = g_w2   + m * DIM + kbase + f4;
            else                       wsrc = g_wres + m * DIM + (kbase - DIM) + f4;
            cp16((unsigned)__cvta_generic_to_shared(Wd + m * AP + f4), wsrc);
        }
        asm volatile("cp.async.commit_group;" ::: "memory");
    };

    float acc[2][8][4];
#pragma unroll
    for (int i = 0; i < 2; i++)
#pragma unroll
        for (int j = 0; j < 8; j++)
#pragma unroll
            for (int r = 0; r < 4; r++) acc[i][j][r] = 0.f;

    load_chunk(0, 0);

#pragma unroll 1
    for (int kc = 0; kc < NCHUNK; kc++) {
        if (kc + 1 < NCHUNK) {
            load_chunk(kc + 1, (kc + 1) & 1);
            asm volatile("cp.async.wait_group 1;" ::: "memory");
        } else {
            asm volatile("cp.async.wait_group 0;" ::: "memory");
        }
        __syncthreads();

        const unsigned* As = Abuf + (kc & 1) * TILEW;
        const unsigned* Ws = Wbuf + (kc & 1) * TILEW;

#pragma unroll
        for (int k8 = 0; k8 < 4; k8++) {
            const int kof = k8 * 8;
            unsigned afrag[2][4];
#pragma unroll
            for (int mt = 0; mt < 2; mt++) {
                int r0 = wm * 32 + mt * 16 + g;
                afrag[mt][0] = As[(r0    ) * AP + kof + tg];
                afrag[mt][1] = As[(r0 + 8) * AP + kof + tg];
                afrag[mt][2] = As[(r0    ) * AP + kof + tg + 4];
                afrag[mt][3] = As[(r0 + 8) * AP + kof + tg + 4];
            }
            unsigned bfrag[8][2];
#pragma unroll
            for (int nt = 0; nt < 8; nt++) {
                int n0 = wn * 64 + nt * 8 + g;
                bfrag[nt][0] = Ws[n0 * AP + kof + tg];
                bfrag[nt][1] = Ws[n0 * AP + kof + tg + 4];
            }
#pragma unroll
            for (int mt = 0; mt < 2; mt++)
#pragma unroll
                for (int nt = 0; nt < 8; nt++)
                    mma_tf32(acc[mt][nt], afrag[mt], bfrag[nt]);
        }
        __syncthreads();
    }

    // ---- epilogue ----
    if (PHASE == 1) {
        float tsum[8][2], tsq[8][2];
#pragma unroll
        for (int nt = 0; nt < 8; nt++)
            tsum[nt][0] = tsum[nt][1] = tsq[nt][0] = tsq[nt][1] = 0.f;

#pragma unroll
        for (int mt = 0; mt < 2; mt++) {
#pragma unroll
            for (int half = 0; half < 2; half++) {
                int gr = rowBase + wm * 32 + mt * 16 + g + half * 8;
                if (gr < M) {
#pragma unroll
                    for (int nt = 0; nt < 8; nt++) {
                        int c = wn * 64 + nt * 8 + tg * 2;
                        float v0 = acc[mt][nt][half * 2 + 0] + __ldg(bias + c);
                        float v1 = acc[mt][nt][half * 2 + 1] + __ldg(bias + c + 1);
                        tsum[nt][0] += v0;  tsum[nt][1] += v1;
                        tsq[nt][0] += v0 * v0;  tsq[nt][1] += v1 * v1;
                        *(float2*)(g_h1 + (size_t)gr * DIM + c) = make_float2(v0, v1);
                    }
                }
            }
        }
#pragma unroll
        for (int nt = 0; nt < 8; nt++) {
#pragma unroll
            for (int h = 0; h < 2; h++) {
#pragma unroll
                for (int ofs = 4; ofs < 32; ofs <<= 1) {
                    tsum[nt][h] += __shfl_xor_sync(0xffffffff, tsum[nt][h], ofs);
                    tsq[nt][h]  += __shfl_xor_sync(0xffffffff, tsq[nt][h], ofs);
                }
            }
        }
        if (g == 0) {
#pragma unroll
            for (int nt = 0; nt < 8; nt++) {
                int c = wn * 64 + nt * 8 + tg * 2;
                atomicAdd(&s_sum[c],     tsum[nt][0]);
                atomicAdd(&s_sum[c + 1], tsum[nt][1]);
                atomicAdd(&s_sq[c],      tsq[nt][0]);
                atomicAdd(&s_sq[c + 1],  tsq[nt][1]);
            }
        }
        __syncthreads();
        if (tid < DIM) {
            atomicAdd(&g_stats[tid],       s_sum[tid]);
            atomicAdd(&g_stats[DIM + tid], s_sq[tid]);
        }
    } else {
#pragma unroll
        for (int mt = 0; mt < 2; mt++) {
#pragma unroll
            for (int half = 0; half < 2; half++) {
                int gr = rowBase + wm * 32 + mt * 16 + g + half * 8;
                if (gr < M) {
#pragma unroll
                    for (int nt = 0; nt < 8; nt++) {
                        int c = wn * 64 + nt * 8 + tg * 2;
                        float v0 = acc[mt][nt][half * 2 + 0] + __ldg(bias + c);
                        float v1 = acc[mt][nt][half * 2 + 1] + __ldg(bias + c + 1);
                        v0 = v0 > 0.f ? v0 : 0.2f * v0;
                        v1 = v1 > 0.f ? v1 : 0.2f * v1;
                        *(float2*)(outp + (size_t)gr * DIM + c) = make_float2(v0, v1);
                    }
                }
            }
        }
    }
}

// ---------------------------------------------------------------------------
extern "C" void kernel_launch(void* const* d_in, const int* in_sizes, int n_in,
                              void* d_out, int out_size) {
    const float* x     = (const float*)d_in[0];
    const int* ei      = (const int*)d_in[1];
    const float* W1    = (const float*)d_in[2];
    const float* b1    = (const float*)d_in[3];
    const float* gamma = (const float*)d_in[4];
    const float* beta  = (const float*)d_in[5];
    const float* W2    = (const float*)d_in[6];
    const float* b2    = (const float*)d_in[7];
    const float* Wres  = (const float*)d_in[8];
    float* out         = (float*)d_out;

    int M = in_sizes[0] / DIM;       // 50000
    int E = in_sizes[1] / 2;         // 600000
    int n4 = M * (DIM / 4);

    static int configured = 0;
    if (!configured) {
        cudaFuncSetAttribute(gemm_kernel<1>,
                             cudaFuncAttributeMaxDynamicSharedMemorySize, SMEM_BYTES);
        cudaFuncSetAttribute(gemm_kernel<2>,
                             cudaFuncAttributeMaxDynamicSharedMemorySize, SMEM_BYTES);
        configured = 1;
    }

    prep_kernel<<<(DIM * DIM + 255) / 256, 256>>>(W1, W2, Wres);
    init_kernel<<<(n4 + 255) / 256, 256>>>(x, n4);
    {
        long long work = (long long)E * 32;
        int blocks = (int)((work + 255) / 256);
        scatter_kernel<<<blocks, 256>>>(x, ei, E);
    }
    int gb = (M + BM - 1) / BM;
    float invM = 1.0f / (float)M;
    gemm_kernel<1><<<gb, 256, SMEM_BYTES>>>(nullptr, b1, nullptr, M);
    bnfix_kernel<<<(n4 + 255) / 256, 256>>>(gamma, beta, invM, n4);
    gemm_kernel<2><<<gb, 256, SMEM_BYTES>>>(x, b2, out, M);
}

// round 8
// speedup vs baseline: 1.3929x; 1.0249x over previous
#include <cuda_runtime.h>
#include <cstdint>

#define DIM 128
#define MAXN 50176
#define BM 128
#define BK 32
#define AP 36                   // padded smem row pitch (words), conflict-free
#define TILEW (BM * AP)         // 4608 words per tile buffer
#define SMEM_BYTES (4 * TILEW * 4)   // 2 A bufs + 2 W bufs = 73728 B

__device__ float g_hpre[MAXN * DIM];       // x + agg
__device__ float g_h1[MAXN * DIM];         // Linear1 out; bnfix transforms in place
__device__ float g_stats[2 * DIM];         // colsum | colsumsq
__device__ unsigned g_w1[DIM * DIM];       // tf32-rounded weights
__device__ unsigned g_w2[DIM * DIM];
__device__ unsigned g_wres[DIM * DIM];

// ---------------------------------------------------------------------------
__device__ __forceinline__ unsigned f2tf(float f) {
    unsigned r;
    asm("cvt.rna.tf32.f32 %0, %1;" : "=r"(r) : "f"(f));
    return r;
}

__device__ __forceinline__ void mma_tf32(float* c, const unsigned* a, const unsigned* b) {
    asm volatile(
        "mma.sync.aligned.m16n8k8.row.col.f32.tf32.tf32.f32 "
        "{%0,%1,%2,%3}, {%4,%5,%6,%7}, {%8,%9}, {%0,%1,%2,%3};"
        : "+f"(c[0]), "+f"(c[1]), "+f"(c[2]), "+f"(c[3])
        : "r"(a[0]), "r"(a[1]), "r"(a[2]), "r"(a[3]), "r"(b[0]), "r"(b[1]));
}

__device__ __forceinline__ void cp16(unsigned smem_dst, const void* gsrc) {
    asm volatile("cp.async.ca.shared.global [%0], [%1], 16;"
                 :: "r"(smem_dst), "l"(gsrc));
}

__device__ __forceinline__ void ldsm4(unsigned& r0, unsigned& r1,
                                      unsigned& r2, unsigned& r3,
                                      const unsigned* p) {
    unsigned addr = (unsigned)__cvta_generic_to_shared(p);
    asm volatile("ldmatrix.sync.aligned.m8n8.x4.shared.b16 {%0,%1,%2,%3}, [%4];"
                 : "=r"(r0), "=r"(r1), "=r"(r2), "=r"(r3) : "r"(addr));
}

// ---------------------------------------------------------------------------
// prep: tf32-round all weight matrices; zero BN stats
// ---------------------------------------------------------------------------
__global__ void prep_kernel(const float* __restrict__ W1,
                            const float* __restrict__ W2,
                            const float* __restrict__ Wres) {
    int i = blockIdx.x * blockDim.x + threadIdx.x;
    if (i < 2 * DIM) g_stats[i] = 0.0f;
    if (i < DIM * DIM) {
        g_w1[i]   = f2tf(W1[i]);
        g_w2[i]   = f2tf(W2[i]);
        g_wres[i] = f2tf(Wres[i]);
    }
}

// ---------------------------------------------------------------------------
__global__ void init_kernel(const float* __restrict__ x, int n4) {
    int gid = blockIdx.x * blockDim.x + threadIdx.x;
    if (gid < n4) ((float4*)g_hpre)[gid] = ((const float4*)x)[gid];
}

// ---------------------------------------------------------------------------
// scatter-add: warp per edge, lane = 4 floats -> LDG.128 + red.global.v4.f32
// ---------------------------------------------------------------------------
__global__ void scatter_kernel(const float* __restrict__ x,
                               const int* __restrict__ ei,
                               int n_edges) {
    int g = blockIdx.x * blockDim.x + threadIdx.x;
    int e = g >> 5;
    int lane = g & 31;
    if (e >= n_edges) return;
    int src = ei[e];
    int dst = ei[n_edges + e];
    const float4* xs = (const float4*)(x + (size_t)src * DIM) + lane;
    float4* hd = (float4*)(g_hpre + (size_t)dst * DIM) + lane;
    float4 v = __ldg(xs);
    asm volatile("red.global.add.v4.f32 [%0], {%1, %2, %3, %4};"
                 :: "l"(hd), "f"(v.x), "f"(v.y), "f"(v.z), "f"(v.w)
                 : "memory");
}

// ---------------------------------------------------------------------------
// bnfix: g_h1 <- tf32_rna( lrelu_0.01( h1 * scale + shift ) )  in place
// ---------------------------------------------------------------------------
__global__ void bnfix_kernel(const float* __restrict__ gamma,
                             const float* __restrict__ beta,
                             float invM, int total4) {
    __shared__ float ssc[DIM];
    __shared__ float ssh[DIM];
    int tid = threadIdx.x;
    if (tid < DIM) {
        float mu  = g_stats[tid] * invM;
        float var = g_stats[DIM + tid] * invM - mu * mu;
        float rstd = rsqrtf(var + 1e-5f);
        float s = gamma[tid] * rstd;
        ssc[tid] = s;
        ssh[tid] = beta[tid] - mu * s;
    }
    __syncthreads();
    int i = blockIdx.x * blockDim.x + tid;
    if (i < total4) {
        float4 v = ((float4*)g_h1)[i];
        int c = (i & 31) * 4;        // DIM/4 = 32 float4 per row
        v.x = fmaf(v.x, ssc[c + 0], ssh[c + 0]);
        v.y = fmaf(v.y, ssc[c + 1], ssh[c + 1]);
        v.z = fmaf(v.z, ssc[c + 2], ssh[c + 2]);
        v.w = fmaf(v.w, ssc[c + 3], ssh[c + 3]);
        v.x = v.x > 0.f ? v.x : 0.01f * v.x;
        v.y = v.y > 0.f ? v.y : 0.01f * v.y;
        v.z = v.z > 0.f ? v.z : 0.01f * v.z;
        v.w = v.w > 0.f ? v.w : 0.01f * v.w;
        v.x = __uint_as_float(f2tf(v.x));
        v.y = __uint_as_float(f2tf(v.y));
        v.z = __uint_as_float(f2tf(v.z));
        v.w = __uint_as_float(f2tf(v.w));
        ((float4*)g_h1)[i] = v;
    }
}

// ---------------------------------------------------------------------------
// Pipelined tf32 GEMM: cp.async double-buffered tiles, ldmatrix fragments.
// PHASE 1: h1 = h_pre @ W1^T + b1 ; BN column sum/sumsq     (K=128)
// PHASE 2: out = lrelu_.2( h1' @ W2^T + x @ Wres^T + b2 )   (K=256)
// ---------------------------------------------------------------------------
template <int PHASE>
__global__ __launch_bounds__(256, 2)
void gemm_kernel(const float* __restrict__ Ax,      // phase2: x
                 const float* __restrict__ bias,
                 float* __restrict__ outp,
                 int M) {
    extern __shared__ unsigned smem[];
    unsigned* Abuf = smem;                 // [2][TILEW]
    unsigned* Wbuf = smem + 2 * TILEW;     // [2][TILEW]
    __shared__ float s_sum[DIM];
    __shared__ float s_sq[DIM];

    const int tid  = threadIdx.x;
    const int wid  = tid >> 5;
    const int lane = tid & 31;
    const int g    = lane >> 2;
    const int tg   = lane & 3;
    const int lm   = lane >> 3;        // ldmatrix: matrix id 0..3
    const int lr   = lane & 7;         // ldmatrix: row within matrix
    const int wm   = wid & 3;
    const int wn   = wid >> 2;
    const int rowBase = blockIdx.x * BM;

    if (PHASE == 1 && tid < DIM) { s_sum[tid] = 0.f; s_sq[tid] = 0.f; }

    const int NCHUNK = (PHASE == 1) ? 4 : 8;

    // ---- chunk loader: 4 x 16B cp.async for A, 4 for W, one commit ----
    auto load_chunk = [&](int kc, int bufidx) {
        const int kbase = kc * BK;
        unsigned* Ad = Abuf + bufidx * TILEW;
        unsigned* Wd = Wbuf + bufidx * TILEW;
#pragma unroll
        for (int t = 0; t < 4; t++) {
            int idx = tid + t * 256;
            int m = idx >> 3;
            int f4 = (idx & 7) * 4;
            const void* asrc;
            if (PHASE == 1) {
                asrc = g_hpre + (size_t)(rowBase + m) * DIM + kbase + f4;
            } else if (kbase < DIM) {
                asrc = g_h1 + (size_t)(rowBase + m) * DIM + kbase + f4;
            } else {
                int gr = rowBase + m;
                if (gr >= M) gr = M - 1;           // x has exactly M rows
                asrc = Ax + (size_t)gr * DIM + (kbase - DIM) + f4;
            }
            cp16((unsigned)__cvta_generic_to_shared(Ad + m * AP + f4), asrc);
            const unsigned* wsrc;
            if (PHASE == 1)            wsrc = g_w1   + m * DIM + kbase + f4;
            else if (kbase < DIM)      wsrc = g_w2   + m * DIM + kbase + f4;
            else                       wsrc = g_wres + m * DIM + (kbase - DIM) + f4;
            cp16((unsigned)__cvta_generic_to_shared(Wd + m * AP + f4), wsrc);
        }
        asm volatile("cp.async.commit_group;" ::: "memory");
    };

    float acc[2][8][4];
#pragma unroll
    for (int i = 0; i < 2; i++)
#pragma unroll
        for (int j = 0; j < 8; j++)
#pragma unroll
            for (int r = 0; r < 4; r++) acc[i][j][r] = 0.f;

    load_chunk(0, 0);

#pragma unroll 1
    for (int kc = 0; kc < NCHUNK; kc++) {
        if (kc + 1 < NCHUNK) {
            load_chunk(kc + 1, (kc + 1) & 1);
            asm volatile("cp.async.wait_group 1;" ::: "memory");
        } else {
            asm volatile("cp.async.wait_group 0;" ::: "memory");
        }
        __syncthreads();

        const unsigned* As = Abuf + (kc & 1) * TILEW;
        const unsigned* Ws = Wbuf + (kc & 1) * TILEW;

#pragma unroll
        for (int k8 = 0; k8 < 4; k8++) {
            const int kof = k8 * 8;
            // A fragments: per mt, one ldmatrix.x4
            //   matrix i -> rows r0+(i&1)*8, cols kof+(i>>1)*4
            unsigned afrag[2][4];
#pragma unroll
            for (int mt = 0; mt < 2; mt++) {
                int r = wm * 32 + mt * 16 + (lm & 1) * 8 + lr;
                ldsm4(afrag[mt][0], afrag[mt][1], afrag[mt][2], afrag[mt][3],
                      As + r * AP + kof + (lm >> 1) * 4);
            }
            // B fragments: per nt-pair, one ldmatrix.x4
            //   matrix i -> rows n0+(i>>1)*8, cols kof+(i&1)*4
            unsigned bfrag[8][2];
#pragma unroll
            for (int ntp = 0; ntp < 4; ntp++) {
                int n = wn * 64 + ntp * 16 + (lm >> 1) * 8 + lr;
                ldsm4(bfrag[2 * ntp][0], bfrag[2 * ntp][1],
                      bfrag[2 * ntp + 1][0], bfrag[2 * ntp + 1][1],
                      Ws + n * AP + kof + (lm & 1) * 4);
            }
#pragma unroll
            for (int mt = 0; mt < 2; mt++)
#pragma unroll
                for (int nt = 0; nt < 8; nt++)
                    mma_tf32(acc[mt][nt], afrag[mt], bfrag[nt]);
        }
        __syncthreads();
    }

    // ---- epilogue ----
    if (PHASE == 1) {
        float tsum[8][2], tsq[8][2];
#pragma unroll
        for (int nt = 0; nt < 8; nt++)
            tsum[nt][0] = tsum[nt][1] = tsq[nt][0] = tsq[nt][1] = 0.f;

#pragma unroll
        for (int mt = 0; mt < 2; mt++) {
#pragma unroll
            for (int half = 0; half < 2; half++) {
                int gr = rowBase + wm * 32 + mt * 16 + g + half * 8;
                if (gr < M) {
#pragma unroll
                    for (int nt = 0; nt < 8; nt++) {
                        int c = wn * 64 + nt * 8 + tg * 2;
                        float v0 = acc[mt][nt][half * 2 + 0] + __ldg(bias + c);
                        float v1 = acc[mt][nt][half * 2 + 1] + __ldg(bias + c + 1);
                        tsum[nt][0] += v0;  tsum[nt][1] += v1;
                        tsq[nt][0] += v0 * v0;  tsq[nt][1] += v1 * v1;
                        *(float2*)(g_h1 + (size_t)gr * DIM + c) = make_float2(v0, v1);
                    }
                }
            }
        }
#pragma unroll
        for (int nt = 0; nt < 8; nt++) {
#pragma unroll
            for (int h = 0; h < 2; h++) {
#pragma unroll
                for (int ofs = 4; ofs < 32; ofs <<= 1) {
                    tsum[nt][h] += __shfl_xor_sync(0xffffffff, tsum[nt][h], ofs);
                    tsq[nt][h]  += __shfl_xor_sync(0xffffffff, tsq[nt][h], ofs);
                }
            }
        }
        if (g == 0) {
#pragma unroll
            for (int nt = 0; nt < 8; nt++) {
                int c = wn * 64 + nt * 8 + tg * 2;
                atomicAdd(&s_sum[c],     tsum[nt][0]);
                atomicAdd(&s_sum[c + 1], tsum[nt][1]);
                atomicAdd(&s_sq[c],      tsq[nt][0]);
                atomicAdd(&s_sq[c + 1],  tsq[nt][1]);
            }
        }
        __syncthreads();
        if (tid < DIM) {
            atomicAdd(&g_stats[tid],       s_sum[tid]);
            atomicAdd(&g_stats[DIM + tid], s_sq[tid]);
        }
    } else {
#pragma unroll
        for (int mt = 0; mt < 2; mt++) {
#pragma unroll
            for (int half = 0; half < 2; half++) {
                int gr = rowBase + wm * 32 + mt * 16 + g + half * 8;
                if (gr < M) {
#pragma unroll
                    for (int nt = 0; nt < 8; nt++) {
                        int c = wn * 64 + nt * 8 + tg * 2;
                        float v0 = acc[mt][nt][half * 2 + 0] + __ldg(bias + c);
                        float v1 = acc[mt][nt][half * 2 + 1] + __ldg(bias + c + 1);
                        v0 = v0 > 0.f ? v0 : 0.2f * v0;
                        v1 = v1 > 0.f ? v1 : 0.2f * v1;
                        *(float2*)(outp + (size_t)gr * DIM + c) = make_float2(v0, v1);
                    }
                }
            }
        }
    }
}

// ---------------------------------------------------------------------------
extern "C" void kernel_launch(void* const* d_in, const int* in_sizes, int n_in,
                              void* d_out, int out_size) {
    const float* x     = (const float*)d_in[0];
    const int* ei      = (const int*)d_in[1];
    const float* W1    = (const float*)d_in[2];
    const float* b1    = (const float*)d_in[3];
    const float* gamma = (const float*)d_in[4];
    const float* beta  = (const float*)d_in[5];
    const float* W2    = (const float*)d_in[6];
    const float* b2    = (const float*)d_in[7];
    const float* Wres  = (const float*)d_in[8];
    float* out         = (float*)d_out;

    int M = in_sizes[0] / DIM;       // 50000
    int E = in_sizes[1] / 2;         // 600000
    int n4 = M * (DIM / 4);

    static int configured = 0;
    if (!configured) {
        cudaFuncSetAttribute(gemm_kernel<1>,
                             cudaFuncAttributeMaxDynamicSharedMemorySize, SMEM_BYTES);
        cudaFuncSetAttribute(gemm_kernel<2>,
                             cudaFuncAttributeMaxDynamicSharedMemorySize, SMEM_BYTES);
        configured = 1;
    }

    prep_kernel<<<(DIM * DIM + 255) / 256, 256>>>(W1, W2, Wres);
    init_kernel<<<(n4 + 255) / 256, 256>>>(x, n4);
    {
        long long work = (long long)E * 32;
        int blocks = (int)((work + 255) / 256);
        scatter_kernel<<<blocks, 256>>>(x, ei, E);
    }
    int gb = (M + BM - 1) / BM;
    float invM = 1.0f / (float)M;
    gemm_kernel<1><<<gb, 256, SMEM_BYTES>>>(nullptr, b1, nullptr, M);
    bnfix_kernel<<<(n4 + 255) / 256, 256>>>(gamma, beta, invM, n4);
    gemm_kernel<2><<<gb, 256, SMEM_BYTES>>>(x, b2, out, M);
}

// round 9
// speedup vs baseline: 1.4636x; 1.0507x over previous
#include <cuda_runtime.h>
#include <cstdint>

#define DIM 128
#define MAXN 50176
#define BM 128
#define BK 32
#define AP 36                   // padded smem row pitch (words), conflict-free
#define TILEW (BM * AP)         // 4608 words per tile buffer
#define SMEM_BYTES (4 * TILEW * 4)   // 2 A bufs + 2 W bufs = 73728 B

__device__ float g_hpre[MAXN * DIM];       // x + agg
__device__ float g_h1[MAXN * DIM];         // Linear1 out (raw, pre-BN)
__device__ float g_stats[2 * DIM];         // colsum | colsumsq
__device__ unsigned g_w1[DIM * DIM];       // tf32-rounded weights
__device__ unsigned g_w2[DIM * DIM];
__device__ unsigned g_wres[DIM * DIM];

// ---------------------------------------------------------------------------
__device__ __forceinline__ unsigned f2tf(float f) {
    unsigned r;
    asm("cvt.rna.tf32.f32 %0, %1;" : "=r"(r) : "f"(f));
    return r;
}

__device__ __forceinline__ void mma_tf32(float* c, const unsigned* a, const unsigned* b) {
    asm volatile(
        "mma.sync.aligned.m16n8k8.row.col.f32.tf32.tf32.f32 "
        "{%0,%1,%2,%3}, {%4,%5,%6,%7}, {%8,%9}, {%0,%1,%2,%3};"
        : "+f"(c[0]), "+f"(c[1]), "+f"(c[2]), "+f"(c[3])
        : "r"(a[0]), "r"(a[1]), "r"(a[2]), "r"(a[3]), "r"(b[0]), "r"(b[1]));
}

__device__ __forceinline__ void cp16(unsigned smem_dst, const void* gsrc) {
    asm volatile("cp.async.ca.shared.global [%0], [%1], 16;"
                 :: "r"(smem_dst), "l"(gsrc));
}

__device__ __forceinline__ void ldsm4(unsigned& r0, unsigned& r1,
                                      unsigned& r2, unsigned& r3,
                                      const unsigned* p) {
    unsigned addr = (unsigned)__cvta_generic_to_shared(p);
    asm volatile("ldmatrix.sync.aligned.m8n8.x4.shared.b16 {%0,%1,%2,%3}, [%4];"
                 : "=r"(r0), "=r"(r1), "=r"(r2), "=r"(r3) : "r"(addr));
}

// ---------------------------------------------------------------------------
// init: copy x -> g_hpre ; round weights ; zero stats   (one launch)
// ---------------------------------------------------------------------------
__global__ void init_kernel(const float* __restrict__ x,
                            const float* __restrict__ W1,
                            const float* __restrict__ W2,
                            const float* __restrict__ Wres, int n4) {
    int gid = blockIdx.x * blockDim.x + threadIdx.x;
    if (gid < 2 * DIM) g_stats[gid] = 0.0f;
    if (gid < DIM * DIM) {
        g_w1[gid]   = f2tf(W1[gid]);
        g_w2[gid]   = f2tf(W2[gid]);
        g_wres[gid] = f2tf(Wres[gid]);
    }
    if (gid < n4) ((float4*)g_hpre)[gid] = ((const float4*)x)[gid];
}

// ---------------------------------------------------------------------------
// scatter-add: warp per edge, lane = 4 floats -> LDG.128 + red.global.v4.f32
// ---------------------------------------------------------------------------
__global__ void scatter_kernel(const float* __restrict__ x,
                               const int* __restrict__ ei,
                               int n_edges) {
    int g = blockIdx.x * blockDim.x + threadIdx.x;
    int e = g >> 5;
    int lane = g & 31;
    if (e >= n_edges) return;
    int src = ei[e];
    int dst = ei[n_edges + e];
    const float4* xs = (const float4*)(x + (size_t)src * DIM) + lane;
    float4* hd = (float4*)(g_hpre + (size_t)dst * DIM) + lane;
    float4 v = __ldg(xs);
    asm volatile("red.global.add.v4.f32 [%0], {%1, %2, %3, %4};"
                 :: "l"(hd), "f"(v.x), "f"(v.y), "f"(v.z), "f"(v.w)
                 : "memory");
}

// ---------------------------------------------------------------------------
// Pipelined tf32 GEMM: cp.async double-buffered tiles, ldmatrix fragments.
// PHASE 1: h1 = h_pre @ W1^T + b1 ; BN column sum/sumsq        (K=128)
// PHASE 2: out = lrelu_.2( bnlrelu(h1) @ W2^T + x @ Wres^T + b2 )  (K=256)
//          BN+leaky+round applied IN SMEM after each h1 chunk lands.
// ---------------------------------------------------------------------------
template <int PHASE>
__global__ __launch_bounds__(256, 2)
void gemm_kernel(const float* __restrict__ Ax,      // phase2: x
                 const float* __restrict__ bias,
                 const float* __restrict__ gamma,
                 const float* __restrict__ beta,
                 float* __restrict__ outp,
                 int M, float invM) {
    extern __shared__ unsigned smem[];
    unsigned* Abuf = smem;                 // [2][TILEW]
    unsigned* Wbuf = smem + 2 * TILEW;     // [2][TILEW]
    __shared__ float s_sum[DIM];
    __shared__ float s_sq[DIM];
    __shared__ float ssc[DIM];
    __shared__ float ssh[DIM];

    const int tid  = threadIdx.x;
    const int wid  = tid >> 5;
    const int lane = tid & 31;
    const int g    = lane >> 2;
    const int tg   = lane & 3;
    const int lm   = lane >> 3;        // ldmatrix: matrix id 0..3
    const int lr   = lane & 7;         // ldmatrix: row within matrix
    const int wm   = wid & 3;
    const int wn   = wid >> 2;
    const int rowBase = blockIdx.x * BM;

    if (PHASE == 1) {
        if (tid < DIM) { s_sum[tid] = 0.f; s_sq[tid] = 0.f; }
    } else {
        if (tid < DIM) {
            float mu  = g_stats[tid] * invM;
            float var = g_stats[DIM + tid] * invM - mu * mu;
            float rstd = rsqrtf(var + 1e-5f);
            float s = gamma[tid] * rstd;
            ssc[tid] = s;
            ssh[tid] = beta[tid] - mu * s;
        }
    }

    const int NCHUNK = (PHASE == 1) ? 4 : 8;

    // ---- chunk loader: 4 x 16B cp.async for A, 4 for W, one commit ----
    auto load_chunk = [&](int kc, int bufidx) {
        const int kbase = kc * BK;
        unsigned* Ad = Abuf + bufidx * TILEW;
        unsigned* Wd = Wbuf + bufidx * TILEW;
#pragma unroll
        for (int t = 0; t < 4; t++) {
            int idx = tid + t * 256;
            int m = idx >> 3;
            int f4 = (idx & 7) * 4;
            const void* asrc;
            if (PHASE == 1) {
                asrc = g_hpre + (size_t)(rowBase + m) * DIM + kbase + f4;
            } else if (kbase < DIM) {
                asrc = g_h1 + (size_t)(rowBase + m) * DIM + kbase + f4;
            } else {
                int gr = rowBase + m;
                if (gr >= M) gr = M - 1;           // x has exactly M rows
                asrc = Ax + (size_t)gr * DIM + (kbase - DIM) + f4;
            }
            cp16((unsigned)__cvta_generic_to_shared(Ad + m * AP + f4), asrc);
            const unsigned* wsrc;
            if (PHASE == 1)            wsrc = g_w1   + m * DIM + kbase + f4;
            else if (kbase < DIM)      wsrc = g_w2   + m * DIM + kbase + f4;
            else                       wsrc = g_wres + m * DIM + (kbase - DIM) + f4;
            cp16((unsigned)__cvta_generic_to_shared(Wd + m * AP + f4), wsrc);
        }
        asm volatile("cp.async.commit_group;" ::: "memory");
    };

    float acc[2][8][4];
#pragma unroll
    for (int i = 0; i < 2; i++)
#pragma unroll
        for (int j = 0; j < 8; j++)
#pragma unroll
            for (int r = 0; r < 4; r++) acc[i][j][r] = 0.f;

    load_chunk(0, 0);

#pragma unroll 1
    for (int kc = 0; kc < NCHUNK; kc++) {
        if (kc + 1 < NCHUNK) {
            load_chunk(kc + 1, (kc + 1) & 1);
            asm volatile("cp.async.wait_group 1;" ::: "memory");
        } else {
            asm volatile("cp.async.wait_group 0;" ::: "memory");
        }
        __syncthreads();

        unsigned* As = Abuf + (kc & 1) * TILEW;
        const unsigned* Ws = Wbuf + (kc & 1) * TILEW;

        // ---- phase2, h1 chunks: BN + leaky + tf32-round in smem ----
        if (PHASE == 2 && kc * BK < DIM) {
            const int kbase = kc * BK;
#pragma unroll
            for (int t = 0; t < 4; t++) {
                int idx = tid + t * 256;
                int m = idx >> 3;
                int f4 = (idx & 7) * 4;
                unsigned* p = As + m * AP + f4;
                float4 v = *(float4*)p;
                int kk = kbase + f4;
                v.x = fmaf(v.x, ssc[kk + 0], ssh[kk + 0]);
                v.y = fmaf(v.y, ssc[kk + 1], ssh[kk + 1]);
                v.z = fmaf(v.z, ssc[kk + 2], ssh[kk + 2]);
                v.w = fmaf(v.w, ssc[kk + 3], ssh[kk + 3]);
                v.x = v.x > 0.f ? v.x : 0.01f * v.x;
                v.y = v.y > 0.f ? v.y : 0.01f * v.y;
                v.z = v.z > 0.f ? v.z : 0.01f * v.z;
                v.w = v.w > 0.f ? v.w : 0.01f * v.w;
                p[0] = f2tf(v.x); p[1] = f2tf(v.y);
                p[2] = f2tf(v.z); p[3] = f2tf(v.w);
            }
            __syncthreads();
        }

#pragma unroll
        for (int k8 = 0; k8 < 4; k8++) {
            const int kof = k8 * 8;
            unsigned afrag[2][4];
#pragma unroll
            for (int mt = 0; mt < 2; mt++) {
                int r = wm * 32 + mt * 16 + (lm & 1) * 8 + lr;
                ldsm4(afrag[mt][0], afrag[mt][1], afrag[mt][2], afrag[mt][3],
                      As + r * AP + kof + (lm >> 1) * 4);
            }
            unsigned bfrag[8][2];
#pragma unroll
            for (int ntp = 0; ntp < 4; ntp++) {
                int n = wn * 64 + ntp * 16 + (lm >> 1) * 8 + lr;
                ldsm4(bfrag[2 * ntp][0], bfrag[2 * ntp][1],
                      bfrag[2 * ntp + 1][0], bfrag[2 * ntp + 1][1],
                      Ws + n * AP + kof + (lm & 1) * 4);
            }
#pragma unroll
            for (int mt = 0; mt < 2; mt++)
#pragma unroll
                for (int nt = 0; nt < 8; nt++)
                    mma_tf32(acc[mt][nt], afrag[mt], bfrag[nt]);
        }
        __syncthreads();
    }

    // ---- epilogue ----
    if (PHASE == 1) {
        float tsum[8][2], tsq[8][2];
#pragma unroll
        for (int nt = 0; nt < 8; nt++)
            tsum[nt][0] = tsum[nt][1] = tsq[nt][0] = tsq[nt][1] = 0.f;

#pragma unroll
        for (int mt = 0; mt < 2; mt++) {
#pragma unroll
            for (int half = 0; half < 2; half++) {
                int gr = rowBase + wm * 32 + mt * 16 + g + half * 8;
                if (gr < M) {
#pragma unroll
                    for (int nt = 0; nt < 8; nt++) {
                        int c = wn * 64 + nt * 8 + tg * 2;
                        float v0 = acc[mt][nt][half * 2 + 0] + __ldg(bias + c);
                        float v1 = acc[mt][nt][half * 2 + 1] + __ldg(bias + c + 1);
                        tsum[nt][0] += v0;  tsum[nt][1] += v1;
                        tsq[nt][0] += v0 * v0;  tsq[nt][1] += v1 * v1;
                        *(float2*)(g_h1 + (size_t)gr * DIM + c) = make_float2(v0, v1);
                    }
                }
            }
        }
#pragma unroll
        for (int nt = 0; nt < 8; nt++) {
#pragma unroll
            for (int h = 0; h < 2; h++) {
#pragma unroll
                for (int ofs = 4; ofs < 32; ofs <<= 1) {
                    tsum[nt][h] += __shfl_xor_sync(0xffffffff, tsum[nt][h], ofs);
                    tsq[nt][h]  += __shfl_xor_sync(0xffffffff, tsq[nt][h], ofs);
                }
            }
        }
        if (g == 0) {
#pragma unroll
            for (int nt = 0; nt < 8; nt++) {
                int c = wn * 64 + nt * 8 + tg * 2;
                atomicAdd(&s_sum[c],     tsum[nt][0]);
                atomicAdd(&s_sum[c + 1], tsum[nt][1]);
                atomicAdd(&s_sq[c],      tsq[nt][0]);
                atomicAdd(&s_sq[c + 1],  tsq[nt][1]);
            }
        }
        __syncthreads();
        if (tid < DIM) {
            atomicAdd(&g_stats[tid],       s_sum[tid]);
            atomicAdd(&g_stats[DIM + tid], s_sq[tid]);
        }
    } else {
#pragma unroll
        for (int mt = 0; mt < 2; mt++) {
#pragma unroll
            for (int half = 0; half < 2; half++) {
                int gr = rowBase + wm * 32 + mt * 16 + g + half * 8;
                if (gr < M) {
#pragma unroll
                    for (int nt = 0; nt < 8; nt++) {
                        int c = wn * 64 + nt * 8 + tg * 2;
                        float v0 = acc[mt][nt][half * 2 + 0] + __ldg(bias + c);
                        float v1 = acc[mt][nt][half * 2 + 1] + __ldg(bias + c + 1);
                        v0 = v0 > 0.f ? v0 : 0.2f * v0;
                        v1 = v1 > 0.f ? v1 : 0.2f * v1;
                        *(float2*)(outp + (size_t)gr * DIM + c) = make_float2(v0, v1);
                    }
                }
            }
        }
    }
}

// ---------------------------------------------------------------------------
extern "C" void kernel_launch(void* const* d_in, const int* in_sizes, int n_in,
                              void* d_out, int out_size) {
    const float* x     = (const float*)d_in[0];
    const int* ei      = (const int*)d_in[1];
    const float* W1    = (const float*)d_in[2];
    const float* b1    = (const float*)d_in[3];
    const float* gamma = (const float*)d_in[4];
    const float* beta  = (const float*)d_in[5];
    const float* W2    = (const float*)d_in[6];
    const float* b2    = (const float*)d_in[7];
    const float* Wres  = (const float*)d_in[8];
    float* out         = (float*)d_out;

    int M = in_sizes[0] / DIM;       // 50000
    int E = in_sizes[1] / 2;         // 600000
    int n4 = M * (DIM / 4);

    static int configured = 0;
    if (!configured) {
        cudaFuncSetAttribute(gemm_kernel<1>,
                             cudaFuncAttributeMaxDynamicSharedMemorySize, SMEM_BYTES);
        cudaFuncSetAttribute(gemm_kernel<2>,
                             cudaFuncAttributeMaxDynamicSharedMemorySize, SMEM_BYTES);
        configured = 1;
    }

    init_kernel<<<(n4 + 255) / 256, 256>>>(x, W1, W2, Wres, n4);
    {
        long long work = (long long)E * 32;
        int blocks = (int)((work + 255) / 256);
        scatter_kernel<<<blocks, 256>>>(x, ei, E);
    }
    int gb = (M + BM - 1) / BM;
    float invM = 1.0f / (float)M;
    gemm_kernel<1><<<gb, 256, SMEM_BYTES>>>(nullptr, b1, nullptr, nullptr, nullptr, M, invM);
    gemm_kernel<2><<<gb, 256, SMEM_BYTES>>>(x, b2, gamma, beta, out, M, invM);
}